// round 9
// baseline (speedup 1.0000x reference)
#include <cuda_runtime.h>
#include <math.h>

#define N_NODES 100000
#define HID 128
#define NF (N_NODES * HID)   // 12,800,000
#define KG 20

// Persistent scratch (allocation-free requirement -> __device__ globals)
__device__ float d_g[NF];     // pre-scaled features  g = (h @ W) * dis[row]
__device__ float d_agg[NF];   // scatter accumulator
__device__ float d_h[NF];     // layer output (post-relu)
__device__ float d_dis[N_NODES];  // deg -> rsqrt(deg)

// ---------------------------------------------------------------------------
// Degree / normalization
// ---------------------------------------------------------------------------
__global__ void k_dis_init() {
    int i = blockIdx.x * blockDim.x + threadIdx.x;
    if (i < N_NODES) d_dis[i] = 1.0f;   // self-loop contributes 1
}

__global__ void k_deg_count(const int* __restrict__ dst, int E) {
    int e = blockIdx.x * blockDim.x + threadIdx.x;
    if (e < E) atomicAdd(&d_dis[dst[e]], 1.0f);
}

__global__ void k_dis_finish() {
    int i = blockIdx.x * blockDim.x + threadIdx.x;
    if (i < N_NODES) d_dis[i] = rsqrtf(d_dis[i]);
}

__global__ void k_zero_agg() {
    int i = blockIdx.x * blockDim.x + threadIdx.x;  // NF/4 threads exactly
    ((float4*)d_agg)[i] = make_float4(0.f, 0.f, 0.f, 0.f);
}

// ---------------------------------------------------------------------------
// GEMM: out[r][c] = dis[r] * sum_k A[r][k] * W[k][c]   (M x 128 @ 128 x 128)
// Tile: 64 rows x 128 cols per block, 256 threads, K chunked by 32.
// Each thread: 8 rows x 4 cols accumulators.
// ---------------------------------------------------------------------------
__global__ void __launch_bounds__(256) k_gemm(const float* __restrict__ A,
                                              const float* __restrict__ W,
                                              int M, int useH) {
    __shared__ float Ws[32 * 128];  // 16 KB
    __shared__ float Xs[64 * 32];   //  8 KB
    const float* Ap = useH ? (const float*)d_h : A;

    int tid  = threadIdx.x;
    int warp = tid >> 5;
    int lane = tid & 31;
    int rowBase = blockIdx.x * 64;

    float acc[8][4];
#pragma unroll
    for (int i = 0; i < 8; i++)
#pragma unroll
        for (int j = 0; j < 4; j++) acc[i][j] = 0.f;

    for (int kc = 0; kc < 4; kc++) {
#pragma unroll
        for (int i = 0; i < 16; i++) {
            int idx = tid + i * 256;
            Ws[idx] = W[kc * 4096 + idx];
        }
#pragma unroll
        for (int i = 0; i < 8; i++) {
            int idx = tid + i * 256;
            int r = idx >> 5, c = idx & 31;
            int gr = rowBase + r;
            Xs[idx] = (gr < M) ? Ap[gr * 128 + kc * 32 + c] : 0.f;
        }
        __syncthreads();

#pragma unroll 4
        for (int k = 0; k < 32; k++) {
            float4 w = *(const float4*)&Ws[k * 128 + lane * 4];
#pragma unroll
            for (int i = 0; i < 8; i++) {
                float xv = Xs[(warp * 8 + i) * 32 + k];
                acc[i][0] += xv * w.x;
                acc[i][1] += xv * w.y;
                acc[i][2] += xv * w.z;
                acc[i][3] += xv * w.w;
            }
        }
        __syncthreads();
    }

#pragma unroll
    for (int i = 0; i < 8; i++) {
        int r = rowBase + warp * 8 + i;
        if (r < M) {
            float s = d_dis[r];
            float4 o = make_float4(acc[i][0] * s, acc[i][1] * s,
                                   acc[i][2] * s, acc[i][3] * s);
            *(float4*)&d_g[r * 128 + lane * 4] = o;
        }
    }
}

// ---------------------------------------------------------------------------
// Scatter: one warp per edge, lane l handles float4 column l.
// agg[dst] += g[src] via vector reduction (red.global.add.v4.f32, sm_90+).
// ---------------------------------------------------------------------------
__global__ void __launch_bounds__(256) k_scatter(const int* __restrict__ src,
                                                 const int* __restrict__ dst,
                                                 int E) {
    int gid = blockIdx.x * 256 + threadIdx.x;
    int e = gid >> 5;
    if (e >= E) return;
    int lane = threadIdx.x & 31;
    int s = __ldg(src + e);
    int d = __ldg(dst + e);

    float4 v = ((const float4*)d_g)[s * 32 + lane];
    float4* ap = ((float4*)d_agg) + (d * 32 + lane);
    asm volatile("red.global.add.v4.f32 [%0], {%1, %2, %3, %4};"
                 :: "l"(ap), "f"(v.x), "f"(v.y), "f"(v.z), "f"(v.w)
                 : "memory");
}

// ---------------------------------------------------------------------------
// Finalize: h = relu(dis[r] * (agg + g) + b[col])
// ---------------------------------------------------------------------------
__global__ void k_finalize(const float* __restrict__ b) {
    int i = blockIdx.x * blockDim.x + threadIdx.x;  // NF/4 threads
    int row = i >> 5;       // (i*4)/128
    int c4  = i & 31;
    float s = d_dis[row];
    float4 a = ((const float4*)d_agg)[i];
    float4 g = ((const float4*)d_g)[i];
    float4 bb = ((const float4*)b)[c4];
    float4 o;
    o.x = fmaxf(fmaf(s, a.x + g.x, bb.x), 0.f);
    o.y = fmaxf(fmaf(s, a.y + g.y, bb.y), 0.f);
    o.z = fmaxf(fmaf(s, a.z + g.z, bb.z), 0.f);
    o.w = fmaxf(fmaf(s, a.w + g.w, bb.w), 0.f);
    ((float4*)d_h)[i] = o;
}

// ---------------------------------------------------------------------------
// MDN heads: per node compute 60 logits (20 pi / 20 mu / 20 log_sigma),
// softmax over pi. Block = 256 threads = 4 groups x 64 threads; each group
// handles 4 nodes (16 nodes/block) so each W load feeds 4 FMAs.
// ---------------------------------------------------------------------------
__global__ void __launch_bounds__(256) k_heads(
    const float* __restrict__ piW, const float* __restrict__ pib,
    const float* __restrict__ muW, const float* __restrict__ mub,
    const float* __restrict__ lsW, const float* __restrict__ lsb,
    float* __restrict__ out) {
    __shared__ float hs[16 * 128];  // 8 KB
    int tid = threadIdx.x;
    int nodeBase = blockIdx.x * 16;
#pragma unroll
    for (int i = 0; i < 8; i++) {
        int idx = tid + i * 256;
        hs[idx] = d_h[nodeBase * 128 + idx];
    }
    __syncthreads();

    int grp = tid >> 6;
    int c   = tid & 63;
    if (c >= 60) return;  // only lanes 60..63 of 2nd warp exit; 1st warp intact

    const float* wp;
    float bias;
    if (c < 20)      { wp = piW + c;        bias = pib[c];      }
    else if (c < 40) { wp = muW + (c - 20); bias = mub[c - 20]; }
    else             { wp = lsW + (c - 40); bias = lsb[c - 40]; }

    const float* h0 = &hs[grp * 4 * 128];
    float z0 = bias, z1 = bias, z2 = bias, z3 = bias;
#pragma unroll 8
    for (int k = 0; k < 128; k++) {
        float w = __ldg(wp + k * KG);
        z0 = fmaf(h0[k],       w, z0);
        z1 = fmaf(h0[128 + k], w, z1);
        z2 = fmaf(h0[256 + k], w, z2);
        z3 = fmaf(h0[384 + k], w, z3);
    }
    float z[4] = {z0, z1, z2, z3};
    int nodeG = nodeBase + grp * 4;

    if (c < 32) {
        // entire first warp of the group (lane == c): pi softmax reductions.
#pragma unroll
        for (int j = 0; j < 4; j++) {
            float m = (c < 20) ? z[j] : -INFINITY;
#pragma unroll
            for (int o = 16; o; o >>= 1)
                m = fmaxf(m, __shfl_xor_sync(0xffffffffu, m, o));
            float e = (c < 20) ? expf(z[j] - m) : 0.f;
            float ss = e;
#pragma unroll
            for (int o = 16; o; o >>= 1)
                ss += __shfl_xor_sync(0xffffffffu, ss, o);
            if (c < 20) out[(nodeG + j) * KG + c] = e / ss;
        }
    }
    if (c >= 20 && c < 40) {
#pragma unroll
        for (int j = 0; j < 4; j++)
            out[N_NODES * KG + (nodeG + j) * KG + (c - 20)] = z[j];
    } else if (c >= 40) {
#pragma unroll
        for (int j = 0; j < 4; j++)
            out[2 * N_NODES * KG + (nodeG + j) * KG + (c - 40)] = z[j];
    }
}

// ---------------------------------------------------------------------------
extern "C" void kernel_launch(void* const* d_in, const int* in_sizes, int n_in,
                              void* d_out, int out_size) {
    const float* x   = (const float*)d_in[0];
    const int*   ei  = (const int*)d_in[1];
    const float* W1  = (const float*)d_in[2];
    const float* b1  = (const float*)d_in[3];
    const float* W2  = (const float*)d_in[4];
    const float* b2  = (const float*)d_in[5];
    const float* piW = (const float*)d_in[6];
    const float* pib = (const float*)d_in[7];
    const float* muW = (const float*)d_in[8];
    const float* mub = (const float*)d_in[9];
    const float* lsW = (const float*)d_in[10];
    const float* lsb = (const float*)d_in[11];
    float* out = (float*)d_out;

    const int E = in_sizes[1] / 2;
    const int* src = ei;
    const int* dst = ei + E;
    const int M = N_NODES;

    const int gN    = (N_NODES + 255) / 256;
    const int gE    = (E + 255) / 256;
    const int gScat = (int)(((long long)E * 32 + 255) / 256);
    const int gElem = NF / 4 / 256;          // 12500
    const int gGemm = (M + 63) / 64;         // 1563
    const int gHead = N_NODES / 16;          // 6250

    // normalization: dis = rsqrt(deg(A+I))
    k_dis_init<<<gN, 256>>>();
    k_deg_count<<<gE, 256>>>(dst, E);
    k_dis_finish<<<gN, 256>>>();

    // layer 1
    k_gemm<<<gGemm, 256>>>(x, W1, M, 0);     // d_g = (x@W1) * dis
    k_zero_agg<<<gElem, 256>>>();
    k_scatter<<<gScat, 256>>>(src, dst, E);  // d_agg += d_g[src]
    k_finalize<<<gElem, 256>>>(b1);          // d_h = relu(dis*(agg+g)+b1)

    // layer 2
    k_gemm<<<gGemm, 256>>>(nullptr, W2, M, 1);  // d_g = (d_h@W2) * dis
    k_zero_agg<<<gElem, 256>>>();
    k_scatter<<<gScat, 256>>>(src, dst, E);
    k_finalize<<<gElem, 256>>>(b2);

    // MDN heads
    k_heads<<<gHead, 256>>>(piW, pib, muW, mub, lsW, lsb, out);
}

// round 10
// speedup vs baseline: 1.6225x; 1.6225x over previous
#include <cuda_runtime.h>
#include <math.h>

#define N_NODES 100000
#define HID 128
#define NF (N_NODES * HID)   // 12,800,000
#define KG 20
#define E_MAX 3200000

// Persistent scratch (allocation-free requirement -> __device__ globals)
__device__ float d_g[NF];          // pre-scaled features  g = (h @ W) * dis[row]
__device__ float d_h[NF];          // layer output (post-relu)
__device__ float d_dis[N_NODES];   // rsqrt(deg+1)
__device__ int   d_deg[N_NODES];
__device__ int   d_off[N_NODES + 1];
__device__ int   d_cursor[N_NODES];
__device__ int   d_csr[E_MAX];     // src indices grouped by dst

// ---------------------------------------------------------------------------
// CSR build: histogram -> scan -> fill
// ---------------------------------------------------------------------------
__global__ void k_deg_zero() {
    int i = blockIdx.x * blockDim.x + threadIdx.x;
    if (i < N_NODES) d_deg[i] = 0;
}

__global__ void k_deg_count(const int* __restrict__ dst, int E) {
    int e = blockIdx.x * blockDim.x + threadIdx.x;
    if (e < E) atomicAdd(&d_deg[dst[e]], 1);
}

// Single-block exclusive scan over N_NODES degrees (1024 threads, ~98 elems each).
__global__ void __launch_bounds__(1024) k_scan() {
    const int T = 1024;
    const int CH = (N_NODES + T - 1) / T;   // 98
    int tid = threadIdx.x;
    int beg = tid * CH;
    int end = beg + CH; if (end > N_NODES) end = N_NODES;

    int s = 0;
    for (int i = beg; i < end; i++) s += d_deg[i];

    __shared__ int wsum[32];
    int lane = tid & 31, wid = tid >> 5;
    int v = s;
#pragma unroll
    for (int o = 1; o < 32; o <<= 1) {
        int t = __shfl_up_sync(0xffffffffu, v, o);
        if (lane >= o) v += t;
    }
    if (lane == 31) wsum[wid] = v;
    __syncthreads();
    if (wid == 0) {
        int w = wsum[lane];
#pragma unroll
        for (int o = 1; o < 32; o <<= 1) {
            int t = __shfl_up_sync(0xffffffffu, w, o);
            if (lane >= o) w += t;
        }
        wsum[lane] = w;
    }
    __syncthreads();

    int run = v - s + (wid ? wsum[wid - 1] : 0);   // exclusive prefix for this chunk
    for (int i = beg; i < end; i++) {
        d_off[i] = run;
        d_cursor[i] = run;
        run += d_deg[i];
    }
    if (tid == T - 1) d_off[N_NODES] = run;
}

__global__ void k_fill(const int* __restrict__ src, const int* __restrict__ dst,
                       int E) {
    int e = blockIdx.x * blockDim.x + threadIdx.x;
    if (e < E) {
        int d = dst[e];
        int pos = atomicAdd(&d_cursor[d], 1);
        d_csr[pos] = src[e];
    }
}

__global__ void k_dis() {
    int i = blockIdx.x * blockDim.x + threadIdx.x;
    if (i < N_NODES) d_dis[i] = rsqrtf((float)(d_deg[i] + 1));  // +1 self-loop
}

// ---------------------------------------------------------------------------
// GEMM: d_g[r][c] = dis[r] * sum_k A[r][k] * W[k][c]   (M x 128 @ 128 x 128)
// Tile: 64 rows x 128 cols per block, 256 threads, K chunked by 32.
// ---------------------------------------------------------------------------
__global__ void __launch_bounds__(256) k_gemm(const float* __restrict__ A,
                                              const float* __restrict__ W,
                                              int M, int useH) {
    __shared__ float Ws[32 * 128];  // 16 KB
    __shared__ float Xs[64 * 32];   //  8 KB
    const float* Ap = useH ? (const float*)d_h : A;

    int tid  = threadIdx.x;
    int warp = tid >> 5;
    int lane = tid & 31;
    int rowBase = blockIdx.x * 64;

    float acc[8][4];
#pragma unroll
    for (int i = 0; i < 8; i++)
#pragma unroll
        for (int j = 0; j < 4; j++) acc[i][j] = 0.f;

    for (int kc = 0; kc < 4; kc++) {
#pragma unroll
        for (int i = 0; i < 16; i++) {
            int idx = tid + i * 256;
            Ws[idx] = W[kc * 4096 + idx];
        }
#pragma unroll
        for (int i = 0; i < 8; i++) {
            int idx = tid + i * 256;
            int r = idx >> 5, c = idx & 31;
            int gr = rowBase + r;
            Xs[idx] = (gr < M) ? Ap[gr * 128 + kc * 32 + c] : 0.f;
        }
        __syncthreads();

#pragma unroll 4
        for (int k = 0; k < 32; k++) {
            float4 w = *(const float4*)&Ws[k * 128 + lane * 4];
#pragma unroll
            for (int i = 0; i < 8; i++) {
                float xv = Xs[(warp * 8 + i) * 32 + k];
                acc[i][0] += xv * w.x;
                acc[i][1] += xv * w.y;
                acc[i][2] += xv * w.z;
                acc[i][3] += xv * w.w;
            }
        }
        __syncthreads();
    }

#pragma unroll
    for (int i = 0; i < 8; i++) {
        int r = rowBase + warp * 8 + i;
        if (r < M) {
            float s = d_dis[r];
            float4 o = make_float4(acc[i][0] * s, acc[i][1] * s,
                                   acc[i][2] * s, acc[i][3] * s);
            *(float4*)&d_g[r * 128 + lane * 4] = o;
        }
    }
}

// ---------------------------------------------------------------------------
// Fused CSR gather + finalize: one warp per node, lane l = float4 column l.
//   h[r] = relu( dis[r] * ( sum_{e in CSR(r)} g[src_e] + g[r] ) + b )
// ---------------------------------------------------------------------------
__global__ void __launch_bounds__(256) k_gather(const float* __restrict__ b) {
    int w = (blockIdx.x * 256 + threadIdx.x) >> 5;
    if (w >= N_NODES) return;
    int lane = threadIdx.x & 31;
    const float4* __restrict__ g4 = (const float4*)d_g;

    float4 acc = g4[w * 32 + lane];   // self-loop term (dis applied below -> dis^2)
    int beg = d_off[w], end = d_off[w + 1];

    for (int e0 = beg; e0 < end; e0 += 32) {
        int n = end - e0; if (n > 32) n = 32;
        int idx = (lane < n) ? d_csr[e0 + lane] : 0;
        int j = 0;
        for (; j + 4 <= n; j += 4) {
            int s0 = __shfl_sync(0xffffffffu, idx, j);
            int s1 = __shfl_sync(0xffffffffu, idx, j + 1);
            int s2 = __shfl_sync(0xffffffffu, idx, j + 2);
            int s3 = __shfl_sync(0xffffffffu, idx, j + 3);
            float4 v0 = g4[s0 * 32 + lane];
            float4 v1 = g4[s1 * 32 + lane];
            float4 v2 = g4[s2 * 32 + lane];
            float4 v3 = g4[s3 * 32 + lane];
            acc.x += (v0.x + v1.x) + (v2.x + v3.x);
            acc.y += (v0.y + v1.y) + (v2.y + v3.y);
            acc.z += (v0.z + v1.z) + (v2.z + v3.z);
            acc.w += (v0.w + v1.w) + (v2.w + v3.w);
        }
        for (; j < n; j++) {
            int s = __shfl_sync(0xffffffffu, idx, j);
            float4 v = g4[s * 32 + lane];
            acc.x += v.x; acc.y += v.y; acc.z += v.z; acc.w += v.w;
        }
    }

    float s = d_dis[w];
    float4 bb = ((const float4*)b)[lane];
    float4 o;
    o.x = fmaxf(fmaf(s, acc.x, bb.x), 0.f);
    o.y = fmaxf(fmaf(s, acc.y, bb.y), 0.f);
    o.z = fmaxf(fmaf(s, acc.z, bb.z), 0.f);
    o.w = fmaxf(fmaf(s, acc.w, bb.w), 0.f);
    ((float4*)d_h)[w * 32 + lane] = o;
}

// ---------------------------------------------------------------------------
// MDN heads: per node 60 logits (20 pi / 20 mu / 20 log_sigma), softmax on pi.
// Block = 256 = 4 groups x 64 threads; each group handles 4 nodes.
// ---------------------------------------------------------------------------
__global__ void __launch_bounds__(256) k_heads(
    const float* __restrict__ piW, const float* __restrict__ pib,
    const float* __restrict__ muW, const float* __restrict__ mub,
    const float* __restrict__ lsW, const float* __restrict__ lsb,
    float* __restrict__ out) {
    __shared__ float hs[16 * 128];  // 8 KB
    int tid = threadIdx.x;
    int nodeBase = blockIdx.x * 16;
#pragma unroll
    for (int i = 0; i < 8; i++) {
        int idx = tid + i * 256;
        hs[idx] = d_h[nodeBase * 128 + idx];
    }
    __syncthreads();

    int grp = tid >> 6;
    int c   = tid & 63;
    if (c >= 60) return;  // only lanes 60..63 of 2nd warp exit; 1st warp intact

    const float* wp;
    float bias;
    if (c < 20)      { wp = piW + c;        bias = pib[c];      }
    else if (c < 40) { wp = muW + (c - 20); bias = mub[c - 20]; }
    else             { wp = lsW + (c - 40); bias = lsb[c - 40]; }

    const float* h0 = &hs[grp * 4 * 128];
    float z0 = bias, z1 = bias, z2 = bias, z3 = bias;
#pragma unroll 8
    for (int k = 0; k < 128; k++) {
        float w = __ldg(wp + k * KG);
        z0 = fmaf(h0[k],       w, z0);
        z1 = fmaf(h0[128 + k], w, z1);
        z2 = fmaf(h0[256 + k], w, z2);
        z3 = fmaf(h0[384 + k], w, z3);
    }
    float z[4] = {z0, z1, z2, z3};
    int nodeG = nodeBase + grp * 4;

    if (c < 32) {
        // entire first warp of the group: pi softmax reductions.
#pragma unroll
        for (int j = 0; j < 4; j++) {
            float m = (c < 20) ? z[j] : -INFINITY;
#pragma unroll
            for (int o = 16; o; o >>= 1)
                m = fmaxf(m, __shfl_xor_sync(0xffffffffu, m, o));
            float e = (c < 20) ? expf(z[j] - m) : 0.f;
            float ss = e;
#pragma unroll
            for (int o = 16; o; o >>= 1)
                ss += __shfl_xor_sync(0xffffffffu, ss, o);
            if (c < 20) out[(nodeG + j) * KG + c] = e / ss;
        }
    }
    if (c >= 20 && c < 40) {
#pragma unroll
        for (int j = 0; j < 4; j++)
            out[N_NODES * KG + (nodeG + j) * KG + (c - 20)] = z[j];
    } else if (c >= 40) {
#pragma unroll
        for (int j = 0; j < 4; j++)
            out[2 * N_NODES * KG + (nodeG + j) * KG + (c - 40)] = z[j];
    }
}

// ---------------------------------------------------------------------------
extern "C" void kernel_launch(void* const* d_in, const int* in_sizes, int n_in,
                              void* d_out, int out_size) {
    const float* x   = (const float*)d_in[0];
    const int*   ei  = (const int*)d_in[1];
    const float* W1  = (const float*)d_in[2];
    const float* b1  = (const float*)d_in[3];
    const float* W2  = (const float*)d_in[4];
    const float* b2  = (const float*)d_in[5];
    const float* piW = (const float*)d_in[6];
    const float* pib = (const float*)d_in[7];
    const float* muW = (const float*)d_in[8];
    const float* mub = (const float*)d_in[9];
    const float* lsW = (const float*)d_in[10];
    const float* lsb = (const float*)d_in[11];
    float* out = (float*)d_out;

    const int E = in_sizes[1] / 2;
    const int* src = ei;
    const int* dst = ei + E;
    const int M = N_NODES;

    const int gN    = (N_NODES + 255) / 256;
    const int gE    = (E + 255) / 256;
    const int gGemm = (M + 63) / 64;                 // 1563
    const int gGath = (N_NODES * 32 + 255) / 256;    // 12500
    const int gHead = N_NODES / 16;                  // 6250

    // CSR build (by dst) + normalization
    k_deg_zero<<<gN, 256>>>();
    k_deg_count<<<gE, 256>>>(dst, E);
    k_scan<<<1, 1024>>>();
    k_fill<<<gE, 256>>>(src, dst, E);
    k_dis<<<gN, 256>>>();

    // layer 1
    k_gemm<<<gGemm, 256>>>(x, W1, M, 0);     // d_g = (x@W1) * dis
    k_gather<<<gGath, 256>>>(b1);            // d_h = relu(dis*(sum g[src] + g) + b1)

    // layer 2
    k_gemm<<<gGemm, 256>>>(nullptr, W2, M, 1);
    k_gather<<<gGath, 256>>>(b2);

    // MDN heads
    k_heads<<<gHead, 256>>>(piW, pib, muW, mub, lsW, lsb, out);
}